// round 1
// baseline (speedup 1.0000x reference)
#include <cuda_runtime.h>
#include <cuda_bf16.h>
#include <cstdint>

// Problem constants
#define BATCH 32
#define NA 8400
#define NJ 100
#define NC 80
#define KTOP 13
#define EPSV 1e-9f

// ---------------- device scratch (no allocations allowed) ----------------
__device__ float         g_pst[BATCH * NC * NA];   // transposed scores [b][c][a]
__device__ int           g_cnt[BATCH * NA];        // # gts claiming anchor via topk
__device__ int           g_minj[BATCH * NA];       // smallest claiming gt
__device__ int           g_gt[BATCH * NA];         // final assigned gt (0 if none)
__device__ unsigned char g_pos[BATCH * NA];
__device__ float         g_alignsel[BATCH * NA];   // align metric at (assigned gt, anchor)
__device__ unsigned int  g_posalign[BATCH * NJ];   // float bits, atomicMax (nonneg floats)
__device__ unsigned int  g_posovl[BATCH * NJ];
__device__ float         g_normv[BATCH * NA];
__device__ int           g_labv[BATCH * NA];

// ---------------- helpers ----------------
__device__ __forceinline__ float iou_box(float gx1, float gy1, float gx2, float gy2,
                                         float4 p, float garea) {
    float ix1 = fmaxf(gx1, p.x), iy1 = fmaxf(gy1, p.y);
    float ix2 = fminf(gx2, p.z), iy2 = fminf(gy2, p.w);
    float iw = fmaxf(ix2 - ix1, 0.0f), ih = fmaxf(iy2 - iy1, 0.0f);
    float inter = iw * ih;
    float parea = (p.z - p.x) * (p.w - p.y);
    return inter / (garea + parea - inter + EPSV);
}

// ---------------- K_init ----------------
__global__ void k_init() {
    int i = blockIdx.x * blockDim.x + threadIdx.x;
    if (i < BATCH * NA) { g_cnt[i] = 0; g_minj[i] = 0x7FFFFFFF; }
    if (i < BATCH * NJ) { g_posalign[i] = 0u; g_posovl[i] = 0u; }
}

// ---------------- K0: transpose pred_scores [b,a,c] -> [b,c,a] ----------------
__global__ void k_transpose(const float* __restrict__ ps) {
    __shared__ float t[32][33];
    int b  = blockIdx.z;
    int a0 = blockIdx.x * 32;
    int c0 = blockIdx.y * 32;
    for (int i = threadIdx.y; i < 32; i += 8) {
        int a = a0 + i, c = c0 + threadIdx.x;
        float v = 0.0f;
        if (a < NA && c < NC) v = ps[((size_t)b * NA + a) * NC + c];
        t[i][threadIdx.x] = v;
    }
    __syncthreads();
    for (int i = threadIdx.y; i < 32; i += 8) {
        int c = c0 + i, a = a0 + threadIdx.x;
        if (c < NC && a < NA) g_pst[((size_t)b * NC + c) * NA + a] = t[threadIdx.x][i];
    }
}

// ---------------- K1: per (b, j) metrics + exact top-13 + scatter ----------------
__global__ __launch_bounds__(256) void k_topk(
    const float* __restrict__ pb,    // pred_bboxes [b,a,4]
    const float* __restrict__ ap,    // anchor_points [a,2]
    const int*   __restrict__ glab,  // gt_labels [b,j]
    const float* __restrict__ gbb,   // gt_bboxes [b,j,4]
    const float* __restrict__ mgt)   // mask_gt [b,j]
{
    __shared__ float    sm[NA];
    __shared__ unsigned sg[(NA + 31) / 32];
    __shared__ float    s_rv[8];
    __shared__ int      s_ri[8];

    int j = blockIdx.x, b = blockIdx.y;
    if (mgt[b * NJ + j] <= 0.0f) return;  // invalid gt contributes nothing to final mask

    int tid = threadIdx.x;
    for (int w = tid; w < (NA + 31) / 32; w += 256) sg[w] = 0u;

    const float4 gb4 = ((const float4*)gbb)[b * NJ + j];
    const float gx1 = gb4.x, gy1 = gb4.y, gx2 = gb4.z, gy2 = gb4.w;
    const float garea = (gx2 - gx1) * (gy2 - gy1);
    const int   lab = glab[b * NJ + j];
    const float* __restrict__ pst = g_pst + ((size_t)b * NC + lab) * NA;
    __syncthreads();

    for (int a = tid; a < NA; a += 256) {
        float4 p = ((const float4*)pb)[(size_t)b * NA + a];
        float iou = iou_box(gx1, gy1, gx2, gy2, p, garea);
        float2 apt = ((const float2*)ap)[a];
        float m = fminf(fminf(apt.x - gx1, apt.y - gy1),
                        fminf(gx2 - apt.x, gy2 - apt.y));
        bool ingts = m > EPSV;
        float i2 = iou * iou;
        float al = pst[a] * (i2 * i2 * i2);   // score^1 * iou^6
        sm[a] = ingts ? al : 0.0f;            // masked metric used for ranking
        if (ingts) atomicOr(&sg[a >> 5], 1u << (a & 31));
    }
    __syncthreads();

    const int gbase = b * NA;
    for (int it = 0; it < KTOP; ++it) {
        // thread-local best: value desc, index asc (strict > keeps smallest a)
        float bv = -1.0f; int bi = 0x3FFFFFFF;
        for (int a = tid; a < NA; a += 256) {
            float v = sm[a];
            if (v > bv) { bv = v; bi = a; }
        }
        // warp reduce
        #pragma unroll
        for (int off = 16; off; off >>= 1) {
            float ov = __shfl_down_sync(0xFFFFFFFFu, bv, off);
            int   oi = __shfl_down_sync(0xFFFFFFFFu, bi, off);
            if (ov > bv || (ov == bv && oi < bi)) { bv = ov; bi = oi; }
        }
        if ((tid & 31) == 0) { s_rv[tid >> 5] = bv; s_ri[tid >> 5] = bi; }
        __syncthreads();
        if (tid == 0) {
            float fv = s_rv[0]; int fi = s_ri[0];
            #pragma unroll
            for (int w = 1; w < 8; ++w) {
                if (s_rv[w] > fv || (s_rv[w] == fv && s_ri[w] < fi)) { fv = s_rv[w]; fi = s_ri[w]; }
            }
            sm[fi] = -1.0f;  // remove from future selections
            if ((sg[fi >> 5] >> (fi & 31)) & 1u) {  // mask_pos needs is_in_gts too
                atomicAdd(&g_cnt[gbase + fi], 1);
                atomicMin(&g_minj[gbase + fi], j);
            }
        }
        __syncthreads();
    }
}

// ---------------- K3: per-anchor resolution ----------------
__global__ void k_resolve(
    const float* __restrict__ pb,
    const int*   __restrict__ glab,
    const float* __restrict__ gbb)
{
    int i = blockIdx.x * blockDim.x + threadIdx.x;
    if (i >= BATCH * NA) return;
    int b = i / NA;
    int s = g_cnt[i];
    if (s == 0) { g_gt[i] = 0; g_pos[i] = 0; g_alignsel[i] = 0.0f; return; }

    float4 p = ((const float4*)pb)[i];
    int g; float iou;
    if (s == 1) {
        g = g_minj[i];
        float4 gb4 = ((const float4*)gbb)[b * NJ + g];
        iou = iou_box(gb4.x, gb4.y, gb4.z, gb4.w, p,
                      (gb4.z - gb4.x) * (gb4.w - gb4.y));
    } else {
        // anchor claimed by multiple gts -> argmax_j overlaps (first max)
        float best = -1.0f; g = 0;
        for (int j = 0; j < NJ; ++j) {
            float4 gb4 = ((const float4*)gbb)[b * NJ + j];
            float v = iou_box(gb4.x, gb4.y, gb4.z, gb4.w, p,
                              (gb4.z - gb4.x) * (gb4.w - gb4.y));
            if (v > best) { best = v; g = j; }
        }
        iou = best;
    }
    int lab = glab[b * NJ + g];
    float score = g_pst[((size_t)b * NC + lab) * NA + (i % NA)];
    float i2 = iou * iou;
    float al = score * (i2 * i2 * i2);
    g_gt[i] = g; g_pos[i] = 1;
    g_alignsel[i] = al;
    atomicMax(&g_posalign[b * NJ + g], __float_as_uint(al));
    atomicMax(&g_posovl[b * NJ + g], __float_as_uint(iou));
}

// ---------------- K4a: norm + labels + bboxes + pos ----------------
__global__ void k_final_a(
    const int*   __restrict__ glab,
    const float* __restrict__ gbb,
    float* __restrict__ out)
{
    int i = blockIdx.x * blockDim.x + threadIdx.x;
    if (i >= BATCH * NA) return;
    int b = i / NA;
    bool pos = g_pos[i] != 0;
    int g = g_gt[i];
    float norm = 0.0f; int lab = NC;
    if (pos) {
        int r = b * NJ + g;
        float pa = __uint_as_float(g_posalign[r]);
        float po = __uint_as_float(g_posovl[r]);
        norm = g_alignsel[i] * po / (pa + EPSV);
        lab = glab[r];
    }
    // output layout: [labels | bboxes | scores | pos], all f32
    out[i] = (float)lab;
    ((float4*)(out + BATCH * NA))[i] = ((const float4*)gbb)[b * NJ + g];
    out[(size_t)BATCH * NA * 85 + i] = pos ? 1.0f : 0.0f;
    g_normv[i] = norm;
    g_labv[i]  = lab;
}

// ---------------- K4b: one-hot score fill (float4 stores) ----------------
__global__ void k_final_b(float* __restrict__ out) {
    int idx = blockIdx.x * blockDim.x + threadIdx.x;       // over B*A*20 float4s
    if (idx >= BATCH * NA * (NC / 4)) return;
    int i = idx / (NC / 4);
    int q = idx - i * (NC / 4);
    int lab = g_labv[i];
    float norm = g_normv[i];
    float4 v = make_float4(0.f, 0.f, 0.f, 0.f);
    int c0 = q * 4;
    if (lab >= c0 && lab < c0 + 4) {
        float* vp = &v.x;
        vp[lab - c0] = norm;
    }
    float4* scores = (float4*)(out + (size_t)BATCH * NA * 5);
    scores[idx] = v;
}

// ---------------- launch ----------------
extern "C" void kernel_launch(void* const* d_in, const int* in_sizes, int n_in,
                              void* d_out, int out_size) {
    const float* pred_scores  = (const float*)d_in[0];
    const float* pred_bboxes  = (const float*)d_in[1];
    const float* anchor_pts   = (const float*)d_in[2];
    const int*   gt_labels    = (const int*)d_in[3];
    const float* gt_bboxes    = (const float*)d_in[4];
    const float* mask_gt      = (const float*)d_in[5];
    float* out = (float*)d_out;

    k_init<<<(BATCH * NA + 255) / 256, 256>>>();

    dim3 tg((NA + 31) / 32, (NC + 31) / 32, BATCH);
    k_transpose<<<tg, dim3(32, 8)>>>(pred_scores);

    k_topk<<<dim3(NJ, BATCH), 256>>>(pred_bboxes, anchor_pts, gt_labels, gt_bboxes, mask_gt);

    k_resolve<<<(BATCH * NA + 255) / 256, 256>>>(pred_bboxes, gt_labels, gt_bboxes);

    k_final_a<<<(BATCH * NA + 255) / 256, 256>>>(gt_labels, gt_bboxes, out);

    k_final_b<<<(BATCH * NA * (NC / 4) + 255) / 256, 256>>>(out);
}

// round 3
// speedup vs baseline: 2.9338x; 2.9338x over previous
#include <cuda_runtime.h>
#include <cuda_bf16.h>
#include <cstdint>

#define BATCH 32
#define NA 8400
#define NJ 100
#define NC 80
#define KTOP 13
#define EPSV 1e-9f
#define CAND_CAP 1024
#define MAXMULTI 24576   // provable bound: <= 13*100*32/2 = 20800

// ---------------- device scratch ----------------
__device__ int           g_cnt[BATCH * NA];
__device__ int           g_minj[BATCH * NA];
__device__ int           g_gt[BATCH * NA];
__device__ unsigned char g_pos[BATCH * NA];
__device__ float         g_alignsel[BATCH * NA];
__device__ unsigned int  g_posalign[BATCH * NJ];   // float bits, atomicMax
__device__ unsigned int  g_posovl[BATCH * NJ];
__device__ float         g_normv[BATCH * NA];
__device__ int           g_labv[BATCH * NA];
__device__ int           g_multi[MAXMULTI];
__device__ int           g_nmulti;

__device__ __forceinline__ float iou_box(float gx1, float gy1, float gx2, float gy2,
                                         float4 p, float garea) {
    float ix1 = fmaxf(gx1, p.x), iy1 = fmaxf(gy1, p.y);
    float ix2 = fminf(gx2, p.z), iy2 = fminf(gy2, p.w);
    float iw = fmaxf(ix2 - ix1, 0.0f), ih = fmaxf(iy2 - iy1, 0.0f);
    float inter = iw * ih;
    float parea = (p.z - p.x) * (p.w - p.y);
    return inter / (garea + parea - inter + EPSV);
}

// ---------------- K_init ----------------
__global__ void k_init() {
    int i = blockIdx.x * blockDim.x + threadIdx.x;
    if (i < BATCH * NA) { g_cnt[i] = 0; g_minj[i] = 0x7FFFFFFF; }
    if (i < BATCH * NJ) { g_posalign[i] = 0u; g_posovl[i] = 0u; }
    if (i == 0) g_nmulti = 0;
}

// ---------------- K1: per (b,j) compacted candidates + exact top-13 ----------------
__global__ __launch_bounds__(256) void k_topk(
    const float* __restrict__ ps,    // pred_scores [b,a,c]
    const float* __restrict__ pb,    // pred_bboxes [b,a,4]
    const float* __restrict__ ap,    // anchor_points [a,2]
    const int*   __restrict__ glab,  // gt_labels [b,j]
    const float* __restrict__ gbb,   // gt_bboxes [b,j,4]
    const float* __restrict__ mgt)   // mask_gt [b,j]
{
    __shared__ unsigned long long s_cand[CAND_CAP];
    __shared__ int s_n;

    int j = blockIdx.x, b = blockIdx.y;
    if (mgt[b * NJ + j] <= 0.0f) return;

    int tid = threadIdx.x;
    if (tid == 0) s_n = 0;

    const float4 gb4 = ((const float4*)gbb)[b * NJ + j];
    const float gx1 = gb4.x, gy1 = gb4.y, gx2 = gb4.z, gy2 = gb4.w;
    const float garea = (gx2 - gx1) * (gy2 - gy1);
    const int   lab = glab[b * NJ + j];
    __syncthreads();

    // Compaction: in-box test first (cheap), full metric only for in-box anchors
    for (int a = tid; a < NA; a += 256) {
        float2 apt = ((const float2*)ap)[a];
        float m = fminf(fminf(apt.x - gx1, apt.y - gy1),
                        fminf(gx2 - apt.x, gy2 - apt.y));
        if (m > EPSV) {
            float4 p = ((const float4*)pb)[(size_t)b * NA + a];
            float iou = iou_box(gx1, gy1, gx2, gy2, p, garea);
            float sc = ps[((size_t)b * NA + a) * NC + lab];
            float i2 = iou * iou;
            float al = sc * (i2 * i2 * i2);
            int slot = atomicAdd(&s_n, 1);
            if (slot < CAND_CAP)
                s_cand[slot] = ((unsigned long long)__float_as_uint(al) << 32)
                             | (unsigned)(~a);
        }
    }
    __syncthreads();

    // Warp 0 selects top-13 by iterative max (value desc, index asc via ~a)
    if (tid < 32) {
        int n = min(s_n, CAND_CAP);
        const int gbase = b * NA;
        for (int it = 0; it < KTOP && it < n; ++it) {
            unsigned long long bv = 0ULL; int bs = -1;
            for (int c = tid; c < n; c += 32) {
                unsigned long long v = s_cand[c];
                if (v > bv) { bv = v; bs = c; }
            }
            #pragma unroll
            for (int off = 16; off; off >>= 1) {
                unsigned long long ov = __shfl_xor_sync(0xFFFFFFFFu, bv, off);
                int os = __shfl_xor_sync(0xFFFFFFFFu, bs, off);
                if (ov > bv) { bv = ov; bs = os; }
            }
            if ((unsigned)(bv >> 32) == 0u) break;  // only zeros left: never scatter
            if (tid == 0) {
                s_cand[bs] = 0ULL;
                int a = (int)(~(unsigned)bv);
                atomicAdd(&g_cnt[gbase + a], 1);
                atomicMin(&g_minj[gbase + a], j);
            }
            __syncwarp();
        }
    }
}

// ---------------- K2a: uniform resolution; compact multi-claim anchors ----------------
__global__ void k_resolve1(
    const float* __restrict__ ps,
    const float* __restrict__ pb,
    const int*   __restrict__ glab,
    const float* __restrict__ gbb)
{
    int i = blockIdx.x * blockDim.x + threadIdx.x;
    if (i >= BATCH * NA) return;
    int s = g_cnt[i];
    if (s == 0) { g_gt[i] = 0; g_pos[i] = 0; g_alignsel[i] = 0.0f; return; }
    g_pos[i] = 1;
    int b = i / NA;
    if (s == 1) {
        int g = g_minj[i];
        float4 gb4 = ((const float4*)gbb)[b * NJ + g];
        float4 p = ((const float4*)pb)[i];
        float iou = iou_box(gb4.x, gb4.y, gb4.z, gb4.w, p,
                            (gb4.z - gb4.x) * (gb4.w - gb4.y));
        int lab = glab[b * NJ + g];
        float sc = ps[(size_t)i * NC + lab];
        float i2 = iou * iou;
        float al = sc * (i2 * i2 * i2);
        g_gt[i] = g;
        g_alignsel[i] = al;
        atomicMax(&g_posalign[b * NJ + g], __float_as_uint(al));
        atomicMax(&g_posovl[b * NJ + g], __float_as_uint(iou));
    } else {
        int slot = atomicAdd(&g_nmulti, 1);
        g_multi[slot] = i;
    }
}

// ---------------- K2b: warp-per-multi-anchor argmax over 100 GTs ----------------
__global__ __launch_bounds__(256) void k_resolve2(
    const float* __restrict__ ps,
    const float* __restrict__ pb,
    const int*   __restrict__ glab,
    const float* __restrict__ gbb)
{
    int gw = (blockIdx.x * blockDim.x + threadIdx.x) >> 5;
    int lane = threadIdx.x & 31;
    if (gw >= g_nmulti) return;
    int i = g_multi[gw];
    int b = i / NA;
    float4 p = ((const float4*)pb)[i];

    unsigned long long bv = 0ULL;
    for (int j = lane; j < NJ; j += 32) {
        float4 gb4 = ((const float4*)gbb)[b * NJ + j];
        float v = iou_box(gb4.x, gb4.y, gb4.z, gb4.w, p,
                          (gb4.z - gb4.x) * (gb4.w - gb4.y));
        unsigned long long key = ((unsigned long long)__float_as_uint(v) << 32)
                               | (unsigned)(~j);
        bv = max(bv, key);
    }
    #pragma unroll
    for (int off = 16; off; off >>= 1)
        bv = max(bv, __shfl_xor_sync(0xFFFFFFFFu, bv, off));

    if (lane == 0) {
        int g = (int)(~(unsigned)bv);
        float iou = __uint_as_float((unsigned)(bv >> 32));
        int lab = glab[b * NJ + g];
        float sc = ps[(size_t)i * NC + lab];
        float i2 = iou * iou;
        float al = sc * (i2 * i2 * i2);
        g_gt[i] = g;
        g_alignsel[i] = al;
        atomicMax(&g_posalign[b * NJ + g], __float_as_uint(al));
        atomicMax(&g_posovl[b * NJ + g], __float_as_uint(iou));
    }
}

// ---------------- K3a: norm + labels + bboxes + pos ----------------
__global__ void k_final_a(
    const int*   __restrict__ glab,
    const float* __restrict__ gbb,
    float* __restrict__ out)
{
    int i = blockIdx.x * blockDim.x + threadIdx.x;
    if (i >= BATCH * NA) return;
    int b = i / NA;
    bool pos = g_pos[i] != 0;
    int g = g_gt[i];
    float norm = 0.0f; int lab = NC;
    if (pos) {
        int r = b * NJ + g;
        float pa = __uint_as_float(g_posalign[r]);
        float po = __uint_as_float(g_posovl[r]);
        norm = g_alignsel[i] * po / (pa + EPSV);
        lab = glab[r];
    }
    out[i] = (float)lab;
    ((float4*)(out + BATCH * NA))[i] = ((const float4*)gbb)[b * NJ + g];
    out[(size_t)BATCH * NA * 85 + i] = pos ? 1.0f : 0.0f;
    g_normv[i] = norm;
    g_labv[i]  = lab;
}

// ---------------- K3b: one-hot score fill ----------------
__global__ void k_final_b(float* __restrict__ out) {
    int idx = blockIdx.x * blockDim.x + threadIdx.x;
    if (idx >= BATCH * NA * (NC / 4)) return;
    int i = idx / (NC / 4);
    int q = idx - i * (NC / 4);
    int lab = g_labv[i];
    float norm = g_normv[i];
    float4 v = make_float4(0.f, 0.f, 0.f, 0.f);
    int c0 = q * 4;
    if (lab >= c0 && lab < c0 + 4) {
        float* vp = &v.x;
        vp[lab - c0] = norm;
    }
    float4* scores = (float4*)(out + (size_t)BATCH * NA * 5);
    scores[idx] = v;
}

// ---------------- launch ----------------
extern "C" void kernel_launch(void* const* d_in, const int* in_sizes, int n_in,
                              void* d_out, int out_size) {
    const float* pred_scores  = (const float*)d_in[0];
    const float* pred_bboxes  = (const float*)d_in[1];
    const float* anchor_pts   = (const float*)d_in[2];
    const int*   gt_labels    = (const int*)d_in[3];
    const float* gt_bboxes    = (const float*)d_in[4];
    const float* mask_gt      = (const float*)d_in[5];
    float* out = (float*)d_out;

    k_init<<<(BATCH * NA + 255) / 256, 256>>>();

    k_topk<<<dim3(NJ, BATCH), 256>>>(pred_scores, pred_bboxes, anchor_pts,
                                     gt_labels, gt_bboxes, mask_gt);

    k_resolve1<<<(BATCH * NA + 255) / 256, 256>>>(pred_scores, pred_bboxes,
                                                  gt_labels, gt_bboxes);

    // warp per multi-claim anchor; bound MAXMULTI, surplus warps exit on count
    k_resolve2<<<(MAXMULTI * 32 + 255) / 256, 256>>>(pred_scores, pred_bboxes,
                                                     gt_labels, gt_bboxes);

    k_final_a<<<(BATCH * NA + 255) / 256, 256>>>(gt_labels, gt_bboxes, out);

    k_final_b<<<(BATCH * NA * (NC / 4) + 255) / 256, 256>>>(out);
}